// round 6
// baseline (speedup 1.0000x reference)
#include <cuda_runtime.h>
#include <cstdint>

// Inverse 2D Haar DWT, collapsed to the per-2x2-block butterfly:
//   out[2i  ,2j  ] = 0.5*(LL + LH + HL + HH)
//   out[2i  ,2j+1] = 0.5*(LL - LH + HL - HH)
//   out[2i+1,2j  ] = 0.5*(LL + LH - HL - HH)
//   out[2i+1,2j+1] = 0.5*(LL - LH - HL + HH)
//
// Shapes: in (32,128,56,56) f32 x4 -> out (32,128,112,112) f32
//
// This round: 256-bit stores (sm_103a STG.256 via st.global.cs.v8.b32).
// Each thread: one float4 (LDG.128, streaming) per subband = 4 input cols,
// producing 8 output cols in each of 2 rows = exactly ONE v8 store per row.
// Warp-level footprint per instruction: loads 512B contiguous per stream,
// stores 1024B contiguous — no split sectors (the R2 failure mode).
//
//   idx = ch*(56*14) + i*14 + jj          (jj = input col quad)
//   in_off  = 4*idx
//   out_off = ch*12544 + 2*i*112 + 8*jj = 16*idx - 8*(idx % 14)

#define W_OUT  112
#define WQUADS 14

__device__ __forceinline__ void stg256_cs(float* p, const float v[8])
{
    asm volatile(
        "st.global.cs.v8.b32 [%0], {%1, %2, %3, %4, %5, %6, %7, %8};"
        :: "l"(p),
           "r"(__float_as_uint(v[0])), "r"(__float_as_uint(v[1])),
           "r"(__float_as_uint(v[2])), "r"(__float_as_uint(v[3])),
           "r"(__float_as_uint(v[4])), "r"(__float_as_uint(v[5])),
           "r"(__float_as_uint(v[6])), "r"(__float_as_uint(v[7]))
        : "memory");
}

__global__ __launch_bounds__(256)
void idwt_haar_kernel(const float* __restrict__ LL,
                      const float* __restrict__ LH,
                      const float* __restrict__ HL,
                      const float* __restrict__ HH,
                      float* __restrict__ out)
{
    unsigned idx = blockIdx.x * blockDim.x + threadIdx.x;   // exact grid, no tail

    unsigned jj      = idx % WQUADS;
    long     in_off  = 4L * idx;
    long     out_off = 16L * idx - 8L * jj;

    float4 ll = __ldcs(reinterpret_cast<const float4*>(LL + in_off));
    float4 lh = __ldcs(reinterpret_cast<const float4*>(LH + in_off));
    float4 hl = __ldcs(reinterpret_cast<const float4*>(HL + in_off));
    float4 hh = __ldcs(reinterpret_cast<const float4*>(HH + in_off));

    float a[4] = {ll.x, ll.y, ll.z, ll.w};
    float b[4] = {lh.x, lh.y, lh.z, lh.w};
    float c[4] = {hl.x, hl.y, hl.z, hl.w};
    float d[4] = {hh.x, hh.y, hh.z, hh.w};

    float ev[8], od[8];
    #pragma unroll
    for (int k = 0; k < 4; k++) {
        float p = a[k] + c[k];   // LL + HL
        float m = a[k] - c[k];   // LL - HL
        float q = b[k] + d[k];   // LH + HH
        float r = b[k] - d[k];   // LH - HH
        ev[2 * k]     = 0.5f * (p + q);
        ev[2 * k + 1] = 0.5f * (p - q);
        od[2 * k]     = 0.5f * (m + r);
        od[2 * k + 1] = 0.5f * (m - r);
    }

    stg256_cs(out + out_off,         ev);
    stg256_cs(out + out_off + W_OUT, od);
}

extern "C" void kernel_launch(void* const* d_in, const int* in_sizes, int n_in,
                              void* d_out, int out_size)
{
    const float* LL = (const float*)d_in[0];
    const float* LH = (const float*)d_in[1];
    const float* HL = (const float*)d_in[2];
    const float* HH = (const float*)d_in[3];
    float* out = (float*)d_out;

    int total   = in_sizes[0] / 4;          // 1,605,632 = 6272 * 256 exactly
    int threads = 256;
    int blocks  = total / threads;          // exact division, no remainder

    idwt_haar_kernel<<<blocks, threads>>>(LL, LH, HL, HH, out);
}

// round 7
// speedup vs baseline: 1.0185x; 1.0185x over previous
#include <cuda_runtime.h>

// Inverse 2D Haar DWT, collapsed to the per-2x2-block butterfly:
//   out[2i  ,2j  ] = 0.5*(LL + LH + HL + HH)
//   out[2i  ,2j+1] = 0.5*(LL - LH + HL - HH)
//   out[2i+1,2j  ] = 0.5*(LL + LH - HL - HH)
//   out[2i+1,2j+1] = 0.5*(LL - LH - HL + HH)
//
// Shapes: in (32,128,56,56) f32 x4 -> out (32,128,112,112) f32
//
// CONVERGED configuration (best harness + best-equal ncu across 6 rounds):
//  - one input column-pair per thread; float2 streaming loads, perfectly
//    linear across the grid (in_off = 2*idx) -> 256B/warp per subband
//  - two float4 streaming stores per thread, contiguous across the warp
//    per output row -> 512B/warp per instruction, no split sectors
//  - exact grid (6,422,528 = 25088 x 256), no tail predicate
//  - index math collapsed to a single %28:
//      out_off = 8*idx - 4*(idx % 28)
// Measured: 6.27 TB/s HBM (79% of spec) = mixed read/write stream ceiling;
// all compute pipes <14%, issue <18%. No bytes left to remove (411MB min).

#define W_OUT  112
#define WPAIRS 28

__global__ __launch_bounds__(256)
void idwt_haar_kernel(const float* __restrict__ LL,
                      const float* __restrict__ LH,
                      const float* __restrict__ HL,
                      const float* __restrict__ HH,
                      float* __restrict__ out)
{
    unsigned idx = blockIdx.x * blockDim.x + threadIdx.x;   // exact grid, no tail

    unsigned jj      = idx % WPAIRS;
    long     in_off  = 2L * idx;
    long     out_off = 8L * idx - 4L * jj;

    float2 ll = __ldcs(reinterpret_cast<const float2*>(LL + in_off));
    float2 lh = __ldcs(reinterpret_cast<const float2*>(LH + in_off));
    float2 hl = __ldcs(reinterpret_cast<const float2*>(HL + in_off));
    float2 hh = __ldcs(reinterpret_cast<const float2*>(HH + in_off));

    float p0 = ll.x + hl.x, m0 = ll.x - hl.x;
    float q0 = lh.x + hh.x, r0 = lh.x - hh.x;
    float p1 = ll.y + hl.y, m1 = ll.y - hl.y;
    float q1 = lh.y + hh.y, r1 = lh.y - hh.y;

    float4 row_even = make_float4(0.5f * (p0 + q0), 0.5f * (p0 - q0),
                                  0.5f * (p1 + q1), 0.5f * (p1 - q1));
    float4 row_odd  = make_float4(0.5f * (m0 + r0), 0.5f * (m0 - r0),
                                  0.5f * (m1 + r1), 0.5f * (m1 - r1));

    __stcs(reinterpret_cast<float4*>(out + out_off),         row_even);
    __stcs(reinterpret_cast<float4*>(out + out_off + W_OUT), row_odd);
}

extern "C" void kernel_launch(void* const* d_in, const int* in_sizes, int n_in,
                              void* d_out, int out_size)
{
    const float* LL = (const float*)d_in[0];
    const float* LH = (const float*)d_in[1];
    const float* HL = (const float*)d_in[2];
    const float* HH = (const float*)d_in[3];
    float* out = (float*)d_out;

    int total   = in_sizes[0] / 2;          // 6,422,528 = 25088 * 256 exactly
    int threads = 256;
    int blocks  = total / threads;          // exact division, no remainder

    idwt_haar_kernel<<<blocks, threads>>>(LL, LH, HL, HH, out);
}